// round 5
// baseline (speedup 1.0000x reference)
#include <cuda_runtime.h>

// LegoConv2d on GB300 — R4: instruction-mix surgery on the per-(b,h) slab GEMM.
// feat[64 x 256pad] = lego[64 x 192] @ X[192 x 256pad], fused one-hot epilogue.
// Columns padded 224->256 (col = i*64 + w, w<56 real) so:
//   * b-side loads are 2x LDS.128 per k-step (was 7x LDS.32)
//   * all index math is shift/mask (was div/mod by 56/224)
// Loads go directly into register arrays (no MOV copies). lego staged once.

#define BATCH   32
#define IN_C    256
#define OUT_C   256
#define NSPLIT  4
#define NLEGO   64
#define BASIC_C 64
#define HIN     56
#define WIN     56
#define HOUT    19
#define WOUT    58
#define KTOT    192
#define KC      64            // X K-chunk staged in smem (3 chunks)
#define NCHUNK  3
#define NCOLP   256           // padded merged columns: i*64 + w

// smem: lego_s[192][64] (48KB) + X_s[KC][256] (64KB) = 112KB -> 2 CTAs/SM
#define SMEM_FLOATS (KTOT*NLEGO + KC*NCOLP)

__device__ int   g_idx[NSPLIT * OUT_C];
__device__ float g_coef[NSPLIT * OUT_C];

// -------- prep: first-max argmax (matches jnp.argmax) + coefficient pick
__global__ void prep_kernel(const float* __restrict__ coefs,
                            const float* __restrict__ comb) {
    int t = blockIdx.x * blockDim.x + threadIdx.x;   // t = i*256 + o
    if (t >= NSPLIT * OUT_C) return;
    const float* c = comb + (size_t)t * NLEGO;
    float bv = c[0];
    int bi = 0;
    #pragma unroll
    for (int n = 1; n < NLEGO; n++) {
        float v = c[n];
        if (v > bv) { bv = v; bi = n; }
    }
    g_idx[t]  = bi;
    g_coef[t] = coefs[(size_t)t * NLEGO + bi];
}

extern __shared__ float smem[];

__global__ __launch_bounds__(256, 2)
void main_kernel(const float* __restrict__ x,
                 const float* __restrict__ lego,
                 float* __restrict__ out) {
    const int h = blockIdx.x;   // 0..18
    const int b = blockIdx.y;   // 0..31
    const int t = threadIdx.x;

    float* lego_s = smem;                    // [KTOT][64]  lego_s[k][n]
    float* X_s    = smem + KTOT * NLEGO;     // [KC][256]   X_s[kk][i*64+w]

    const int cg = t & 31;    // col group: cols [8cg, 8cg+8)
    const int ng = t >> 5;    // row group: rows [8ng, 8ng+8)  (warp-uniform)

    // ---- stage lego once, transposed: lego_s[k][n] = lego[n][k]
    // s = n*192 + k ; gmem coalesced. One-time cost.
    for (int s = t; s < NLEGO * KTOT; s += 256) {
        int n = s >> 7;            // s / 128 — careful: KTOT=192, use real div
        // (recompute properly below)
        n = s / KTOT;
        int k = s - n * KTOT;
        lego_s[k * NLEGO + n] = lego[s];
    }

    // per-thread fixed staging column: col = t -> (i, w)
    const int xi = t >> 6;          // split 0..3
    const int xw = t & 63;          // 0..63 ; only w<56 real
    const float* xb = x + ((size_t)(b * IN_C + xi * BASIC_C) * HIN) * WIN + xw;
    const bool wok = (xw < WIN);

    float acc[8][8];
    #pragma unroll
    for (int r = 0; r < 8; r++)
        #pragma unroll
        for (int j = 0; j < 8; j++) acc[r][j] = 0.f;

    const float* lp = lego_s + 8 * ng;
    const float* xp = X_s + 8 * cg;

    for (int kc = 0; kc < NCHUNK; kc++) {
        const int k0 = kc * KC;

        // ---- stage X chunk: X_s[kk][t] = x[b, xi*64+c, 3h+kh-1, xw]
        //      with k0+kk = c*3 + kh ; kk = loop iteration (col fixed = t)
        #pragma unroll 4
        for (int kk = 0; kk < KC; kk++) {
            int k  = k0 + kk;
            int c  = k / 3;
            int kh = k - c * 3;
            int y  = 3 * h + kh - 1;          // <= 55 always
            float v = 0.f;
            if (wok && y >= 0)
                v = xb[(c * HIN + y) * WIN];
            X_s[kk * NCOLP + t] = v;
        }
        __syncthreads();

        // ---- GEMM over this chunk: 64 FFMA + 4 LDS.128 per k-step
        #pragma unroll 4
        for (int kk = 0; kk < KC; kk++) {
            float a[8], bv[8];
            *(float4*)&a[0]  = *(const float4*)(lp + (k0 + kk) * NLEGO);
            *(float4*)&a[4]  = *(const float4*)(lp + (k0 + kk) * NLEGO + 4);
            *(float4*)&bv[0] = *(const float4*)(xp + kk * NCOLP);
            *(float4*)&bv[4] = *(const float4*)(xp + kk * NCOLP + 4);
            #pragma unroll
            for (int r = 0; r < 8; r++)
                #pragma unroll
                for (int j = 0; j < 8; j++)
                    acc[r][j] = fmaf(a[r], bv[j], acc[r][j]);
        }
        __syncthreads();   // reads done before restaging
    }

    // ---- dump feat into smem (reuse X_s): feat_s[n][i*64+w], 64x256 = 16384 fl
    float* feat_s = X_s;
    #pragma unroll
    for (int r = 0; r < 8; r++) {
        #pragma unroll
        for (int j = 0; j < 8; j += 4)
            *(float4*)(feat_s + (8 * ng + r) * NCOLP + 8 * cg + j) =
                *(float4*)&acc[r][j];
    }
    __syncthreads();

    // ---- fused gather epilogue: out[b,o,h,w+1] = sum_i coef[i,o]*feat[idx][i*64+w]
    for (int s = t; s < OUT_C * 56; s += 256) {
        int o = s / 56;
        int w = s - o * 56;
        float v = 0.f;
        #pragma unroll
        for (int i = 0; i < NSPLIT; i++) {
            int   id = g_idx[i * OUT_C + o];
            float cf = g_coef[i * OUT_C + o];
            v = fmaf(cf, feat_s[id * NCOLP + i * 64 + w], v);
        }
        out[((size_t)(b * OUT_C + o) * HOUT + h) * WOUT + (w + 1)] = v;
    }
    // exact-zero borders (w = 0 and w = 57)
    for (int s = t; s < OUT_C * 2; s += 256) {
        int o  = s >> 1;
        int ww = (s & 1) ? (WOUT - 1) : 0;
        out[((size_t)(b * OUT_C + o) * HOUT + h) * WOUT + ww] = 0.f;
    }
}

extern "C" void kernel_launch(void* const* d_in, const int* in_sizes, int n_in,
                              void* d_out, int out_size) {
    const float* x     = (const float*)d_in[0];   // 32*256*56*56
    const float* lego  = (const float*)d_in[1];   // 64*64*3*1
    const float* coefs = (const float*)d_in[2];   // 4*256*64
    const float* comb  = (const float*)d_in[3];   // 4*256*64
    float* out = (float*)d_out;                   // 32*256*19*58

    (void)in_sizes; (void)n_in; (void)out_size;

    cudaFuncSetAttribute(main_kernel,
                         cudaFuncAttributeMaxDynamicSharedMemorySize,
                         SMEM_FLOATS * (int)sizeof(float));

    prep_kernel<<<4, 256>>>(coefs, comb);
    main_kernel<<<dim3(HOUT, BATCH), 256, SMEM_FLOATS * (int)sizeof(float)>>>(x, lego, out);
}